// round 5
// baseline (speedup 1.0000x reference)
#include <cuda_runtime.h>
#include <math.h>

// EMD loss: per-sample RMS of cumsum(p - q) over C=10, mean over B.
// Register-direct version: each thread owns 2 consecutive samples = 20 floats
// = 5 aligned float4 per array, loaded straight to registers (10 independent
// LDG.128 per thread; L1 merges the 80B-strided sectors so DRAM efficiency
// is 100%). No smem staging, no hot-loop barriers. Fused final reduction via
// threadfence ticket (atomicInc wraparound -> graph-replay safe), fixed-order
// double accumulation -> deterministic.

#define C_DIM 10
#define TPB   256
#define SAMPLES_PER_BLOCK (TPB * 2)     // 512
#define MAX_BLOCKS 65536

__device__ float    g_partials[MAX_BLOCKS];
__device__ unsigned g_ticket;           // zero-init; wraps to 0 each launch

__device__ __forceinline__ float rms_cumsum10(const float* d) {
    float run = 0.0f, acc = 0.0f;
    #pragma unroll
    for (int c = 0; c < C_DIM; c++) {
        run += d[c];
        acc = fmaf(run, run, acc);
    }
    return sqrtf(acc * (1.0f / C_DIM));
}

__global__ void emd_fused_kernel(const float* __restrict__ p,
                                 const float* __restrict__ q,
                                 int B, float inv_B,
                                 float* __restrict__ out) {
    __shared__ float warp_sums[TPB / 32];
    __shared__ bool  is_last;

    const int lane = threadIdx.x & 31;
    const int wid  = threadIdx.x >> 5;
    const int s0 = (blockIdx.x * TPB + threadIdx.x) * 2;   // first of 2 samples

    float thread_acc = 0.0f;

    if (s0 + 2 <= B) {
        // 80-byte chunk per thread, 16B-aligned (s0*10*4 = s0*40, s0 even -> 80B multiple).
        const float4* __restrict__ p4 =
            reinterpret_cast<const float4*>(p + (long long)s0 * C_DIM);
        const float4* __restrict__ q4 =
            reinterpret_cast<const float4*>(q + (long long)s0 * C_DIM);

        float4 a0 = p4[0], a1 = p4[1], a2 = p4[2], a3 = p4[3], a4 = p4[4];
        float4 b0 = q4[0], b1 = q4[1], b2 = q4[2], b3 = q4[3], b4 = q4[4];

        float d[20];
        d[0]  = a0.x - b0.x; d[1]  = a0.y - b0.y; d[2]  = a0.z - b0.z; d[3]  = a0.w - b0.w;
        d[4]  = a1.x - b1.x; d[5]  = a1.y - b1.y; d[6]  = a1.z - b1.z; d[7]  = a1.w - b1.w;
        d[8]  = a2.x - b2.x; d[9]  = a2.y - b2.y; d[10] = a2.z - b2.z; d[11] = a2.w - b2.w;
        d[12] = a3.x - b3.x; d[13] = a3.y - b3.y; d[14] = a3.z - b3.z; d[15] = a3.w - b3.w;
        d[16] = a4.x - b4.x; d[17] = a4.y - b4.y; d[18] = a4.z - b4.z; d[19] = a4.w - b4.w;

        thread_acc = rms_cumsum10(d) + rms_cumsum10(d + C_DIM);
    } else {
        // Tail: scalar guarded (at most one partial thread-pair at the very end).
        for (int s = s0; s < B && s < s0 + 2; s++) {
            const long long rb = (long long)s * C_DIM;
            float run = 0.0f, acc = 0.0f;
            #pragma unroll
            for (int c = 0; c < C_DIM; c++) {
                run += p[rb + c] - q[rb + c];
                acc = fmaf(run, run, acc);
            }
            thread_acc += sqrtf(acc * (1.0f / C_DIM));
        }
    }

    // ---- Block reduction ----
    #pragma unroll
    for (int off = 16; off; off >>= 1)
        thread_acc += __shfl_xor_sync(0xffffffffu, thread_acc, off);
    if (lane == 0) warp_sums[wid] = thread_acc;
    __syncthreads();

    if (wid == 0) {
        float v = (lane < TPB / 32) ? warp_sums[lane] : 0.0f;
        #pragma unroll
        for (int off = 4; off; off >>= 1)
            v += __shfl_xor_sync(0xffffffffu, v, off);
        if (lane == 0) {
            g_partials[blockIdx.x] = v;
            __threadfence();
            unsigned t = atomicInc(&g_ticket, gridDim.x - 1);  // wraps -> 0 each launch
            is_last = (t == gridDim.x - 1);
        }
    }
    __syncthreads();

    if (!is_last) return;

    // ---- Last block: fixed-order double reduction over grid partials ----
    __threadfence();
    __shared__ double dsums[TPB / 32];
    const int n_blocks = gridDim.x;
    double s = 0.0;
    for (int i = threadIdx.x; i < n_blocks; i += TPB)
        s += (double)g_partials[i];

    #pragma unroll
    for (int off = 16; off; off >>= 1)
        s += __shfl_xor_sync(0xffffffffu, s, off);
    if (lane == 0) dsums[wid] = s;
    __syncthreads();

    if (wid == 0) {
        double v = (lane < TPB / 32) ? dsums[lane] : 0.0;
        #pragma unroll
        for (int off = 4; off; off >>= 1)
            v += __shfl_xor_sync(0xffffffffu, v, off);
        if (lane == 0) *out = (float)(v * (double)inv_B);
    }
}

extern "C" void kernel_launch(void* const* d_in, const int* in_sizes, int n_in,
                              void* d_out, int out_size) {
    const float* p = (const float*)d_in[0];
    const float* q = (const float*)d_in[1];
    // d_in[2] is r; setup fixes r=2 (square + sqrt hardcoded).

    const int total = in_sizes[0];       // B * C
    const int B = total / C_DIM;
    const int blocks = (B + SAMPLES_PER_BLOCK - 1) / SAMPLES_PER_BLOCK;  // 4096

    emd_fused_kernel<<<blocks, TPB>>>(p, q, B, 1.0f / (float)B, (float*)d_out);
}

// round 6
// speedup vs baseline: 1.1249x; 1.1249x over previous
#include <cuda_runtime.h>
#include <math.h>

// EMD loss: per-sample RMS of cumsum(p - q) over C=10, mean over B.
// Grid-strided tile loop: 1184 blocks (8/SM, full 2048-thread occupancy),
// each block streams ~7 tiles of 256 samples through a double-buffered
// 2x10.24KB smem diff stage (coalesced float4 LDG -> sub -> STS, one
// __syncthreads per tile). Fused final reduction via threadfence ticket
// (atomicInc wraparound -> graph-replay safe; 1184 blocks so ticket cost
// is ~1us), fixed-order double accumulation -> deterministic.

#define C_DIM 10
#define TPB   256
#define SPT   256                        // samples per tile
#define TILE_FLOATS (SPT * C_DIM)        // 2560
#define TILE_F4     (TILE_FLOATS / 4)    // 640
#define GRID_BLOCKS 1184                 // 8 x 148 SMs
#define MAX_BLOCKS  4096

__device__ float    g_partials[MAX_BLOCKS];
__device__ unsigned g_ticket;            // zero-init; wraps to 0 each launch

__device__ __forceinline__ void stage_tile(const float* __restrict__ p,
                                           const float* __restrict__ q,
                                           float* __restrict__ buf,
                                           long long tile, int valid) {
    if (valid == SPT) {
        const float4* __restrict__ p4 = reinterpret_cast<const float4*>(p) + tile * TILE_F4;
        const float4* __restrict__ q4 = reinterpret_cast<const float4*>(q) + tile * TILE_F4;
        float4* b4 = reinterpret_cast<float4*>(buf);
        #pragma unroll
        for (int i = threadIdx.x; i < TILE_F4; i += TPB) {
            float4 a = p4[i];
            float4 b = q4[i];
            float4 d;
            d.x = a.x - b.x; d.y = a.y - b.y;
            d.z = a.z - b.z; d.w = a.w - b.w;
            b4[i] = d;
        }
    } else {
        const long long base = tile * TILE_FLOATS;
        const int n = valid * C_DIM;
        for (int i = threadIdx.x; i < n; i += TPB)
            buf[i] = p[base + i] - q[base + i];
    }
}

__global__ void __launch_bounds__(TPB, 8)
emd_fused_kernel(const float* __restrict__ p,
                 const float* __restrict__ q,
                 int B, float inv_B,
                 float* __restrict__ out) {
    __shared__ float sd[2][TILE_FLOATS];     // 2 x 10.24 KB diff buffers
    __shared__ float warp_sums[TPB / 32];
    __shared__ bool  is_last;

    const int lane = threadIdx.x & 31;
    const int wid  = threadIdx.x >> 5;
    const int n_tiles = (B + SPT - 1) / SPT;

    float thread_acc = 0.0f;

    long long tile = blockIdx.x;
    if (tile < n_tiles) {
        int valid0 = min(SPT, B - (int)(tile * SPT));
        stage_tile(p, q, sd[0], tile, valid0);
    }
    __syncthreads();

    int parity = 0;
    for (; tile < n_tiles; tile += gridDim.x) {
        // Stage next tile into the other buffer (overlaps with consumption).
        long long next = tile + gridDim.x;
        if (next < n_tiles) {
            int validn = min(SPT, B - (int)(next * SPT));
            stage_tile(p, q, sd[parity ^ 1], next, validn);
        }

        // Consume current tile: one sample per thread.
        int valid = min(SPT, B - (int)(tile * SPT));
        if (threadIdx.x < valid) {
            const float* row = sd[parity] + threadIdx.x * C_DIM;
            float run = 0.0f, acc = 0.0f;
            #pragma unroll
            for (int c = 0; c < C_DIM; c++) {
                run += row[c];
                acc = fmaf(run, run, acc);
            }
            thread_acc += sqrtf(acc * (1.0f / C_DIM));
        }

        parity ^= 1;
        __syncthreads();   // next tile staged + current buffer free for reuse
    }

    // ---- Block reduction ----
    #pragma unroll
    for (int off = 16; off; off >>= 1)
        thread_acc += __shfl_xor_sync(0xffffffffu, thread_acc, off);
    if (lane == 0) warp_sums[wid] = thread_acc;
    __syncthreads();

    if (wid == 0) {
        float v = (lane < TPB / 32) ? warp_sums[lane] : 0.0f;
        #pragma unroll
        for (int off = 4; off; off >>= 1)
            v += __shfl_xor_sync(0xffffffffu, v, off);
        if (lane == 0) {
            g_partials[blockIdx.x] = v;
            __threadfence();
            unsigned t = atomicInc(&g_ticket, gridDim.x - 1);  // wraps -> 0 each launch
            is_last = (t == gridDim.x - 1);
        }
    }
    __syncthreads();

    if (!is_last) return;

    // ---- Last block: fixed-order double reduction over grid partials ----
    __threadfence();
    __shared__ double dsums[TPB / 32];
    const int n_blocks = gridDim.x;
    double s = 0.0;
    for (int i = threadIdx.x; i < n_blocks; i += TPB)
        s += (double)g_partials[i];

    #pragma unroll
    for (int off = 16; off; off >>= 1)
        s += __shfl_xor_sync(0xffffffffu, s, off);
    if (lane == 0) dsums[wid] = s;
    __syncthreads();

    if (wid == 0) {
        double v = (lane < TPB / 32) ? dsums[lane] : 0.0;
        #pragma unroll
        for (int off = 4; off; off >>= 1)
            v += __shfl_xor_sync(0xffffffffu, v, off);
        if (lane == 0) *out = (float)(v * (double)inv_B);
    }
}

extern "C" void kernel_launch(void* const* d_in, const int* in_sizes, int n_in,
                              void* d_out, int out_size) {
    const float* p = (const float*)d_in[0];
    const float* q = (const float*)d_in[1];
    // d_in[2] is r; setup fixes r=2 (square + sqrt hardcoded).

    const int total = in_sizes[0];       // B * C
    const int B = total / C_DIM;
    const int n_tiles = (B + SPT - 1) / SPT;
    const int blocks = n_tiles < GRID_BLOCKS ? n_tiles : GRID_BLOCKS;

    emd_fused_kernel<<<blocks, TPB>>>(p, q, B, 1.0f / (float)B, (float*)d_out);
}